// round 8
// baseline (speedup 1.0000x reference)
#include <cuda_runtime.h>
#include <cuda_fp16.h>
#include <cstdint>

// ConvTranspose2d x(16,256,64,64) w(256,128,4,4) b(128) s=2 p=1 -> (16,128,128,128)
// Parity-class GEMM: D[pix=128, co=128] = A[pix, K=1024] * B[co, K]^T
// R7: single-pass fp16 (A = fp16(x), B = fp16(w)), fp32 accum.
// cp.async staging, XS double-buffer prefetch, ldmatrix + mma.sync m16n8k16.f16.

#define NCHUNK 16
#define OFF_B  0                       // 16384: w fp16, pre-swizzled 128B rows
#define OFF_A  16384                   // 16384: A fp16, swizzled 128B rows
#define OFF_XS 32768                   // 2 x 13824B: [cil16][r3][72 floats]
#define XS_ROW 72
#define XS_BUF_B 13824
#define SMEM_BYTES (32768 + 2 * XS_BUF_B)

__device__ __align__(1024) unsigned char g_wB[4][NCHUNK][16384];

__global__ void prep_wB(const float* __restrict__ w) {
    int idx = blockIdx.x * blockDim.x + threadIdx.x;
    if (idx >= (1 << 19)) return;
    int kq    = idx & 63;
    int co    = (idx >> 6) & 127;
    int chunk = (idx >> 13) & 15;
    int par   = idx >> 17;
    int py = par >> 1, px = par & 1;
    int cil = kq >> 2, ri = (kq >> 1) & 1, jx = kq & 1;
    int ci = chunk * 16 + cil;
    int ky = 3 - py - 2 * ri;
    int kx = 3 - px - 2 * jx;
    float v = w[((ci * 128 + co) * 4 + ky) * 4 + kx];
    uint32_t off = (uint32_t)co * 128 + (uint32_t)kq * 2;
    uint32_t sw = off ^ ((off >> 3) & 0x70);
    *(__half*)(&g_wB[par][chunk][sw]) = __float2half_rn(v);
}

__device__ __forceinline__ uint32_t smem_u32(const void* p) {
    uint32_t a;
    asm("{ .reg .u64 t; cvta.to.shared.u64 t, %1; cvt.u32.u64 %0, t; }" : "=r"(a) : "l"(p));
    return a;
}
__device__ __forceinline__ void cp16(uint32_t dst, const void* src, uint32_t srcsz) {
    asm volatile("cp.async.cg.shared.global [%0], [%1], 16, %2;"
                 :: "r"(dst), "l"(src), "r"(srcsz) : "memory");
}
__device__ __forceinline__ void ldsm4(uint32_t& r0, uint32_t& r1, uint32_t& r2, uint32_t& r3,
                                      uint32_t addr) {
    asm volatile("ldmatrix.sync.aligned.m8n8.x4.shared.b16 {%0,%1,%2,%3}, [%4];"
                 : "=r"(r0), "=r"(r1), "=r"(r2), "=r"(r3) : "r"(addr));
}
__device__ __forceinline__ void mma16816(float* c, const uint32_t* a, const uint32_t* b) {
    asm volatile(
        "mma.sync.aligned.m16n8k16.row.col.f32.f16.f16.f32 "
        "{%0,%1,%2,%3}, {%4,%5,%6,%7}, {%8,%9}, {%0,%1,%2,%3};"
        : "+f"(c[0]), "+f"(c[1]), "+f"(c[2]), "+f"(c[3])
        : "r"(a[0]), "r"(a[1]), "r"(a[2]), "r"(a[3]), "r"(b[0]), "r"(b[1]));
}

__global__ __launch_bounds__(256, 2)
void convt_mma(const float* __restrict__ x,
               const float* __restrict__ bias,
               float* __restrict__ out) {
    extern __shared__ char sm[];
    const int tid = threadIdx.x;
    const int l   = tid & 31;
    const int w   = tid >> 5;
    const int warp_m = w >> 2;
    const int warp_n = w & 3;
    const int yt  = blockIdx.x;
    const int par = blockIdx.y;
    const int n   = blockIdx.z;
    const int py = par >> 1, px = par & 1;

    const uint32_t smb = smem_u32(sm);
    float* XS0 = (float*)(sm + OFF_XS);

    // ---- prezero XS pad cols (both buffers): cols 0-3 and 68-71 ----
    for (int e = tid; e < 192; e += 256) {
        int side = e & 1, t = e >> 1;
        int r = t % 3, rem = t / 3;
        int cil = rem & 15, buf = rem >> 4;
        float4* p = (float4*)(XS0 + buf * (XS_BUF_B / 4) + (cil * 3 + r) * XS_ROW + side * 68);
        *p = make_float4(0.f, 0.f, 0.f, 0.f);
    }

    float acc[4][4][4];
#pragma unroll
    for (int mi = 0; mi < 4; mi++)
#pragma unroll
        for (int nj = 0; nj < 4; nj++)
#pragma unroll
            for (int q = 0; q < 4; q++) acc[mi][nj][q] = 0.0f;

    const int arow_off = (l & 7) + ((l >> 3) & 1) * 8;
    const int ahalf    = l >> 4;
    const int brow_off = (l & 7) + (l >> 4) * 8;
    const int bhalf    = (l >> 3) & 1;

    const int R = 2 * yt - 1 + py;
    const float* xb = x + (size_t)n * 256 * 4096;

    // ---- precomputed XS cp.async descriptors (3 per thread) ----
    uint32_t xs_dst[3], xs_fill[3];
    const float* xs_src[3];
#pragma unroll
    for (int j = 0; j < 3; j++) {
        int e = tid + j * 256;
        int i16 = e & 15, t = e >> 4;
        int r = t % 3, cil = t / 3;
        int iy = R + r;
        bool valid = (iy >= 0 && iy < 64);
        xs_fill[j] = valid ? 16u : 0u;
        int iyc = valid ? iy : 0;
        xs_src[j] = xb + ((size_t)cil << 12) + (iyc << 6) + i16 * 4;
        xs_dst[j] = (uint32_t)(((cil * 3 + r) * XS_ROW + 4 + i16 * 4) * 4);
    }

    // A-build mapping: thread -> (pixel, interleaved cil half)
    const int ap  = tid >> 1;
    const int akh = tid & 1;
    const int arp = ap >> 6, ax2 = ap & 63;
    const int ac0 = ax2 + px + 3;
    const uint32_t a_xorm = (uint32_t)(ap & 7) << 4;
    const uint32_t a_base = (uint32_t)ap * 128;

    // ---- prefetch XS[0] ----
#pragma unroll
    for (int j = 0; j < 3; j++)
        cp16(smb + OFF_XS + xs_dst[j], xs_src[j], xs_fill[j]);
    asm volatile("cp.async.commit_group;" ::: "memory");

    for (int c = 0; c < NCHUNK; c++) {
        const int buf = c & 1;
        asm volatile("cp.async.wait_group 0;" ::: "memory");   // XS[c] ready
        __syncthreads();

        // ---- issue B[c] (group), then XS[c+1] (group) ----
        {
            const char* bsrc = (const char*)g_wB[par][c] + tid * 16;
            const uint32_t bdst = smb + OFF_B + (uint32_t)tid * 16;
#pragma unroll
            for (int i = 0; i < 4; i++)
                cp16(bdst + i * 4096, bsrc + i * 4096, 16);
            asm volatile("cp.async.commit_group;" ::: "memory");
        }
        if (c + 1 < NCHUNK) {
            const size_t coff = (size_t)(c + 1) << 16;
            const uint32_t dst0 = smb + OFF_XS + (buf ^ 1) * XS_BUF_B;
#pragma unroll
            for (int j = 0; j < 3; j++)
                cp16(dst0 + xs_dst[j], xs_src[j] + coff, xs_fill[j]);
        }
        asm volatile("cp.async.commit_group;" ::: "memory");

        // ---- A build: im2col -> fp16, swizzled smem ----
        {
            const float* xsb = (const float*)(sm + OFF_XS + buf * XS_BUF_B);
#pragma unroll
            for (int q = 0; q < 8; q++) {
                const int cil = akh + 2 * q;
#pragma unroll
                for (int ri = 0; ri < 2; ri++) {
                    const float* row = xsb + (cil * 3 + arp + ri) * XS_ROW;
                    float v0 = row[ac0];
                    float v1 = row[ac0 + 1];
                    uint32_t hp;
                    asm("cvt.rn.f16x2.f32 %0, %1, %2;" : "=r"(hp) : "f"(v1), "f"(v0));
                    const uint32_t ao = a_base + (((uint32_t)(cil * 2 + ri) * 4) ^ a_xorm);
                    *(uint32_t*)(sm + OFF_A + ao) = hp;
                }
            }
        }
        asm volatile("cp.async.wait_group 1;" ::: "memory");   // B[c] ready
        __syncthreads();

        // ---- MMA ----
#pragma unroll
        for (int ks = 0; ks < 4; ks++) {
            uint32_t a[4][4], b[4][2];
            const uint32_t akb = (uint32_t)(ks * 32 + ahalf * 16);
#pragma unroll
            for (int mi = 0; mi < 4; mi++) {
                const int row = warp_m * 64 + mi * 16 + arow_off;
                ldsm4(a[mi][0], a[mi][1], a[mi][2], a[mi][3],
                      smb + OFF_A + (uint32_t)row * 128 + (akb ^ (((uint32_t)row & 7) << 4)));
            }
            const uint32_t bkb = (uint32_t)(ks * 32 + bhalf * 16);
#pragma unroll
            for (int bi = 0; bi < 2; bi++) {
                const int row = warp_n * 32 + bi * 16 + brow_off;
                const uint32_t off = (uint32_t)row * 128 + (bkb ^ (((uint32_t)row & 7) << 4));
                uint32_t r0, r1, r2, r3;
                ldsm4(r0, r1, r2, r3, smb + OFF_B + off);
                b[bi * 2][0] = r0;     b[bi * 2][1] = r1;
                b[bi * 2 + 1][0] = r2; b[bi * 2 + 1][1] = r3;
            }
#pragma unroll
            for (int mi = 0; mi < 4; mi++)
#pragma unroll
                for (int nj = 0; nj < 4; nj++)
                    mma16816(acc[mi][nj], a[mi], b[nj]);
        }
        __syncthreads();
    }

    // ---- epilogue ----
    const int prow = l >> 2;
    const int pcol = (l & 3) * 2;
#pragma unroll
    for (int nj = 0; nj < 4; nj++) {
        const int co0 = warp_n * 32 + nj * 8 + pcol;
        const float b0 = __ldg(&bias[co0]);
        const float b1 = __ldg(&bias[co0 + 1]);
        float* o0 = out + ((size_t)(n * 128 + co0) << 14);
        float* o1 = out + ((size_t)(n * 128 + co0 + 1) << 14);
#pragma unroll
        for (int mi = 0; mi < 4; mi++) {
#pragma unroll
            for (int h = 0; h < 2; h++) {
                const int pix = warp_m * 64 + mi * 16 + prow + h * 8;
                const int oy = 2 * (2 * yt + (pix >> 6)) + py;
                const int ox = 2 * (pix & 63) + px;
                const int off = (oy << 7) + ox;
                o0[off] = acc[mi][nj][h * 2 + 0] + b0;
                o1[off] = acc[mi][nj][h * 2 + 1] + b1;
            }
        }
    }
}

extern "C" void kernel_launch(void* const* d_in, const int* in_sizes, int n_in,
                              void* d_out, int out_size) {
    const float* x    = (const float*)d_in[0];
    const float* w    = (const float*)d_in[1];
    const float* bias = (const float*)d_in[2];
    float* out        = (float*)d_out;

    cudaFuncSetAttribute(convt_mma, cudaFuncAttributeMaxDynamicSharedMemorySize, SMEM_BYTES);

    prep_wB<<<(1 << 19) / 256, 256>>>(w);

    dim3 grid(32, 4, 16);
    convt_mma<<<grid, 256, SMEM_BYTES>>>(x, bias, out);
}